// round 1
// baseline (speedup 1.0000x reference)
#include <cuda_runtime.h>
#include <cstdint>

#define B_DIM   32
#define D_DIM   256
#define T_DIM   2048
#define K_CODES 1024
#define N_TOT   (B_DIM * T_DIM)
#define Q_ELEMS (B_DIM * D_DIM * T_DIM)
#define LOSS_OFF Q_ELEMS
#define IDX_OFF  (Q_ELEMS + 1)

#define TN 64
#define XS_PITCH 68
#define ES_PITCH 36

__device__ float g_enorm[K_CODES];

// Precompute 0.5*||e_k||^2 and zero the loss accumulator slot in d_out.
__global__ void enorm_kernel(const float* __restrict__ E, float* __restrict__ out) {
    int gtid = blockIdx.x * blockDim.x + threadIdx.x;
    if (gtid == 0) out[LOSS_OFF] = 0.0f;
    int w = gtid >> 5, lane = gtid & 31;
    if (w < K_CODES) {
        const float* er = E + (size_t)w * D_DIM;
        float s = 0.f;
        for (int d = lane; d < D_DIM; d += 32) { float v = er[d]; s = fmaf(v, v, s); }
        #pragma unroll
        for (int o = 16; o; o >>= 1) s += __shfl_down_sync(0xffffffffu, s, o);
        if (lane == 0) g_enorm[w] = 0.5f * s;
    }
}

// Argmin over k of (0.5*||e_k||^2 - x_n . e_k).
// Block: 256 threads, tile of 64 n, loops all K=1024 codes.
// X tile (64 n x 256 d) resident in smem; E streamed in 64k x 32d chunks.
__global__ void __launch_bounds__(256) argmin_kernel(const float* __restrict__ X,
                                                     const float* __restrict__ E,
                                                     float* __restrict__ out) {
    extern __shared__ float sm[];
    float* Xs = sm;                         // [256][XS_PITCH]
    float* Es = sm + D_DIM * XS_PITCH;      // [64][ES_PITCH]
    float* RedV = Es;                       // reused after main loop: [16][64]
    int*   RedI = (int*)(Es + 16 * 64);     // [16][64]

    const int tid = threadIdx.x;
    const int tx = tid & 15, ty = tid >> 4;
    const int n0 = blockIdx.x * TN;
    const int b  = n0 / T_DIM;
    const int t0 = n0 % T_DIM;
    const float* xbase = X + (size_t)b * D_DIM * T_DIM + t0;

    // Load X tile: transposed to Xs[d][n], coalesced along t.
    {
        int n4 = (tid & 15) * 4;
        for (int d = tid >> 4; d < D_DIM; d += 16) {
            float4 v = *(const float4*)(xbase + (size_t)d * T_DIM + n4);
            *(float4*)(Xs + d * XS_PITCH + n4) = v;
        }
    }

    float bestv[4];
    int   besti[4];
    #pragma unroll
    for (int i = 0; i < 4; i++) { bestv[i] = 3.4e38f; besti[i] = 0; }

    for (int kt = 0; kt < K_CODES / 64; kt++) {
        const int k0 = kt * 64;
        float acc[4][4];
        #pragma unroll
        for (int i = 0; i < 4; i++)
            #pragma unroll
            for (int j = 0; j < 4; j++) acc[i][j] = 0.f;

        for (int dc = 0; dc < D_DIM / 32; dc++) {
            __syncthreads();
            // Load E chunk: 64 rows x 32 d = 512 float4, 2 per thread.
            #pragma unroll
            for (int q = 0; q < 2; q++) {
                int id = tid + q * 256;
                int row = id >> 3, c4 = id & 7;
                float4 v = *(const float4*)(E + (size_t)(k0 + row) * D_DIM + dc * 32 + c4 * 4);
                *(float4*)(Es + row * ES_PITCH + c4 * 4) = v;
            }
            __syncthreads();
            #pragma unroll
            for (int dd = 0; dd < 32; dd++) {
                float4 xv = *(const float4*)(Xs + (dc * 32 + dd) * XS_PITCH + tx * 4);
                float e0 = Es[(ty * 4 + 0) * ES_PITCH + dd];
                float e1 = Es[(ty * 4 + 1) * ES_PITCH + dd];
                float e2 = Es[(ty * 4 + 2) * ES_PITCH + dd];
                float e3 = Es[(ty * 4 + 3) * ES_PITCH + dd];
                acc[0][0] = fmaf(xv.x, e0, acc[0][0]);
                acc[0][1] = fmaf(xv.x, e1, acc[0][1]);
                acc[0][2] = fmaf(xv.x, e2, acc[0][2]);
                acc[0][3] = fmaf(xv.x, e3, acc[0][3]);
                acc[1][0] = fmaf(xv.y, e0, acc[1][0]);
                acc[1][1] = fmaf(xv.y, e1, acc[1][1]);
                acc[1][2] = fmaf(xv.y, e2, acc[1][2]);
                acc[1][3] = fmaf(xv.y, e3, acc[1][3]);
                acc[2][0] = fmaf(xv.z, e0, acc[2][0]);
                acc[2][1] = fmaf(xv.z, e1, acc[2][1]);
                acc[2][2] = fmaf(xv.z, e2, acc[2][2]);
                acc[2][3] = fmaf(xv.z, e3, acc[2][3]);
                acc[3][0] = fmaf(xv.w, e0, acc[3][0]);
                acc[3][1] = fmaf(xv.w, e1, acc[3][1]);
                acc[3][2] = fmaf(xv.w, e2, acc[3][2]);
                acc[3][3] = fmaf(xv.w, e3, acc[3][3]);
            }
        }
        // Fold into per-thread running argmin. k ascending => strict '<'
        // preserves first-min tie-break within the thread's k subset.
        #pragma unroll
        for (int j = 0; j < 4; j++) {
            int k = k0 + ty * 4 + j;
            float en = g_enorm[k];
            #pragma unroll
            for (int i = 0; i < 4; i++) {
                float sc = en - acc[i][j];
                if (sc < bestv[i]) { bestv[i] = sc; besti[i] = k; }
            }
        }
    }

    // Cross-thread reduction over the 16 ty-groups (disjoint k subsets).
    __syncthreads();
    #pragma unroll
    for (int i = 0; i < 4; i++) {
        RedV[ty * 64 + tx * 4 + i] = bestv[i];
        RedI[ty * 64 + tx * 4 + i] = besti[i];
    }
    __syncthreads();
    if (tid < TN) {
        float bv = RedV[tid];
        int   bi = RedI[tid];
        #pragma unroll
        for (int r = 1; r < 16; r++) {
            float v = RedV[r * 64 + tid];
            int  ii = RedI[r * 64 + tid];
            if (v < bv || (v == bv && ii < bi)) { bv = v; bi = ii; }
        }
        out[IDX_OFF + n0 + tid] = (float)bi;
    }
}

// Gather codebook rows, write quantized [B,D,T], accumulate commitment loss.
__global__ void __launch_bounds__(256) gather_loss_kernel(const float* __restrict__ X,
                                                          const float* __restrict__ E,
                                                          float* __restrict__ out) {
    __shared__ float warpsum[8];
    int t = blockIdx.x * 256 + threadIdx.x;
    int b = blockIdx.y;
    int n = b * T_DIM + t;
    int j = (int)out[IDX_OFF + n];
    const float* er = E + (size_t)j * D_DIM;
    const float* xr = X + (size_t)b * D_DIM * T_DIM + t;
    float* orow = out + (size_t)b * D_DIM * T_DIM + t;

    float s = 0.f;
    #pragma unroll 8
    for (int d = 0; d < D_DIM; d += 4) {
        float4 e4 = *(const float4*)(er + d);
        float x0 = xr[(size_t)(d + 0) * T_DIM];
        float x1 = xr[(size_t)(d + 1) * T_DIM];
        float x2 = xr[(size_t)(d + 2) * T_DIM];
        float x3 = xr[(size_t)(d + 3) * T_DIM];
        orow[(size_t)(d + 0) * T_DIM] = e4.x;
        orow[(size_t)(d + 1) * T_DIM] = e4.y;
        orow[(size_t)(d + 2) * T_DIM] = e4.z;
        orow[(size_t)(d + 3) * T_DIM] = e4.w;
        float d0 = e4.x - x0, d1 = e4.y - x1, d2 = e4.z - x2, d3 = e4.w - x3;
        s = fmaf(d0, d0, s);
        s = fmaf(d1, d1, s);
        s = fmaf(d2, d2, s);
        s = fmaf(d3, d3, s);
    }
    #pragma unroll
    for (int o = 16; o; o >>= 1) s += __shfl_down_sync(0xffffffffu, s, o);
    int lane = threadIdx.x & 31, w = threadIdx.x >> 5;
    if (lane == 0) warpsum[w] = s;
    __syncthreads();
    if (threadIdx.x < 8) {
        float v = warpsum[threadIdx.x];
        #pragma unroll
        for (int o = 4; o; o >>= 1) v += __shfl_down_sync(0xffu, v, o);
        if (threadIdx.x == 0)
            atomicAdd(out + LOSS_OFF, v * (0.5f / (float)Q_ELEMS));
    }
}

extern "C" void kernel_launch(void* const* d_in, const int* in_sizes, int n_in,
                              void* d_out, int out_size) {
    const float* X = (const float*)d_in[0];   // [B, D, T] fp32
    const float* E = (const float*)d_in[1];   // [K, D]    fp32
    float* out = (float*)d_out;

    enorm_kernel<<<128, 256>>>(E, out);

    size_t smem = (size_t)(D_DIM * XS_PITCH + 64 * ES_PITCH) * sizeof(float);
    cudaFuncSetAttribute(argmin_kernel, cudaFuncAttributeMaxDynamicSharedMemorySize, (int)smem);
    argmin_kernel<<<N_TOT / TN, 256, smem>>>(X, E, out);

    gather_loss_kernel<<<dim3(T_DIM / 256, B_DIM), 256>>>(X, E, out);
}

// round 2
// speedup vs baseline: 1.0005x; 1.0005x over previous
#include <cuda_runtime.h>
#include <cstdint>

#define B_DIM   32
#define D_DIM   256
#define T_DIM   2048
#define K_CODES 1024
#define N_TOT   (B_DIM * T_DIM)
#define Q_ELEMS (B_DIM * D_DIM * T_DIM)
#define LOSS_OFF Q_ELEMS
#define IDX_OFF  (Q_ELEMS + 1)

#define TN 64
#define XS_PITCH 68
#define ES_PITCH 36

__device__ float g_enorm[K_CODES];

// Precompute 0.5*||e_k||^2 and zero the loss accumulator slot in d_out.
__global__ void enorm_kernel(const float* __restrict__ E, float* __restrict__ out) {
    int gtid = blockIdx.x * blockDim.x + threadIdx.x;
    if (gtid == 0) out[LOSS_OFF] = 0.0f;
    int w = gtid >> 5, lane = gtid & 31;
    if (w < K_CODES) {
        const float* er = E + (size_t)w * D_DIM;
        float s = 0.f;
        for (int d = lane; d < D_DIM; d += 32) { float v = er[d]; s = fmaf(v, v, s); }
        #pragma unroll
        for (int o = 16; o; o >>= 1) s += __shfl_down_sync(0xffffffffu, s, o);
        if (lane == 0) g_enorm[w] = 0.5f * s;
    }
}

// Argmin over k of (0.5*||e_k||^2 - x_n . e_k).
// Block: 256 threads, tile of 64 n, loops all K=1024 codes.
// X tile (64 n x 256 d) resident in smem; E streamed in 64k x 32d chunks.
__global__ void __launch_bounds__(256) argmin_kernel(const float* __restrict__ X,
                                                     const float* __restrict__ E,
                                                     float* __restrict__ out) {
    extern __shared__ float sm[];
    float* Xs = sm;                         // [256][XS_PITCH]
    float* Es = sm + D_DIM * XS_PITCH;      // [64][ES_PITCH]
    float* RedV = Es;                       // reused after main loop: [16][64]
    int*   RedI = (int*)(Es + 16 * 64);     // [16][64]

    const int tid = threadIdx.x;
    const int tx = tid & 15, ty = tid >> 4;
    const int n0 = blockIdx.x * TN;
    const int b  = n0 / T_DIM;
    const int t0 = n0 % T_DIM;
    const float* xbase = X + (size_t)b * D_DIM * T_DIM + t0;

    // Load X tile: transposed to Xs[d][n], coalesced along t.
    {
        int n4 = (tid & 15) * 4;
        for (int d = tid >> 4; d < D_DIM; d += 16) {
            float4 v = *(const float4*)(xbase + (size_t)d * T_DIM + n4);
            *(float4*)(Xs + d * XS_PITCH + n4) = v;
        }
    }

    float bestv[4];
    int   besti[4];
    #pragma unroll
    for (int i = 0; i < 4; i++) { bestv[i] = 3.4e38f; besti[i] = 0; }

    for (int kt = 0; kt < K_CODES / 64; kt++) {
        const int k0 = kt * 64;
        float acc[4][4];
        #pragma unroll
        for (int i = 0; i < 4; i++)
            #pragma unroll
            for (int j = 0; j < 4; j++) acc[i][j] = 0.f;

        for (int dc = 0; dc < D_DIM / 32; dc++) {
            __syncthreads();
            // Load E chunk: 64 rows x 32 d = 512 float4, 2 per thread.
            #pragma unroll
            for (int q = 0; q < 2; q++) {
                int id = tid + q * 256;
                int row = id >> 3, c4 = id & 7;
                float4 v = *(const float4*)(E + (size_t)(k0 + row) * D_DIM + dc * 32 + c4 * 4);
                *(float4*)(Es + row * ES_PITCH + c4 * 4) = v;
            }
            __syncthreads();
            #pragma unroll
            for (int dd = 0; dd < 32; dd++) {
                float4 xv = *(const float4*)(Xs + (dc * 32 + dd) * XS_PITCH + tx * 4);
                float e0 = Es[(ty * 4 + 0) * ES_PITCH + dd];
                float e1 = Es[(ty * 4 + 1) * ES_PITCH + dd];
                float e2 = Es[(ty * 4 + 2) * ES_PITCH + dd];
                float e3 = Es[(ty * 4 + 3) * ES_PITCH + dd];
                acc[0][0] = fmaf(xv.x, e0, acc[0][0]);
                acc[0][1] = fmaf(xv.x, e1, acc[0][1]);
                acc[0][2] = fmaf(xv.x, e2, acc[0][2]);
                acc[0][3] = fmaf(xv.x, e3, acc[0][3]);
                acc[1][0] = fmaf(xv.y, e0, acc[1][0]);
                acc[1][1] = fmaf(xv.y, e1, acc[1][1]);
                acc[1][2] = fmaf(xv.y, e2, acc[1][2]);
                acc[1][3] = fmaf(xv.y, e3, acc[1][3]);
                acc[2][0] = fmaf(xv.z, e0, acc[2][0]);
                acc[2][1] = fmaf(xv.z, e1, acc[2][1]);
                acc[2][2] = fmaf(xv.z, e2, acc[2][2]);
                acc[2][3] = fmaf(xv.z, e3, acc[2][3]);
                acc[3][0] = fmaf(xv.w, e0, acc[3][0]);
                acc[3][1] = fmaf(xv.w, e1, acc[3][1]);
                acc[3][2] = fmaf(xv.w, e2, acc[3][2]);
                acc[3][3] = fmaf(xv.w, e3, acc[3][3]);
            }
        }
        // Fold into per-thread running argmin. k ascending => strict '<'
        // preserves first-min tie-break within the thread's k subset.
        #pragma unroll
        for (int j = 0; j < 4; j++) {
            int k = k0 + ty * 4 + j;
            float en = g_enorm[k];
            #pragma unroll
            for (int i = 0; i < 4; i++) {
                float sc = en - acc[i][j];
                if (sc < bestv[i]) { bestv[i] = sc; besti[i] = k; }
            }
        }
    }

    // Cross-thread reduction over the 16 ty-groups (disjoint k subsets).
    __syncthreads();
    #pragma unroll
    for (int i = 0; i < 4; i++) {
        RedV[ty * 64 + tx * 4 + i] = bestv[i];
        RedI[ty * 64 + tx * 4 + i] = besti[i];
    }
    __syncthreads();
    if (tid < TN) {
        float bv = RedV[tid];
        int   bi = RedI[tid];
        #pragma unroll
        for (int r = 1; r < 16; r++) {
            float v = RedV[r * 64 + tid];
            int  ii = RedI[r * 64 + tid];
            if (v < bv || (v == bv && ii < bi)) { bv = v; bi = ii; }
        }
        out[IDX_OFF + n0 + tid] = (float)bi;
    }
}

// Gather codebook rows, write quantized [B,D,T], accumulate commitment loss.
__global__ void __launch_bounds__(256) gather_loss_kernel(const float* __restrict__ X,
                                                          const float* __restrict__ E,
                                                          float* __restrict__ out) {
    __shared__ float warpsum[8];
    int t = blockIdx.x * 256 + threadIdx.x;
    int b = blockIdx.y;
    int n = b * T_DIM + t;
    int j = (int)out[IDX_OFF + n];
    const float* er = E + (size_t)j * D_DIM;
    const float* xr = X + (size_t)b * D_DIM * T_DIM + t;
    float* orow = out + (size_t)b * D_DIM * T_DIM + t;

    float s = 0.f;
    #pragma unroll 8
    for (int d = 0; d < D_DIM; d += 4) {
        float4 e4 = *(const float4*)(er + d);
        float x0 = xr[(size_t)(d + 0) * T_DIM];
        float x1 = xr[(size_t)(d + 1) * T_DIM];
        float x2 = xr[(size_t)(d + 2) * T_DIM];
        float x3 = xr[(size_t)(d + 3) * T_DIM];
        orow[(size_t)(d + 0) * T_DIM] = e4.x;
        orow[(size_t)(d + 1) * T_DIM] = e4.y;
        orow[(size_t)(d + 2) * T_DIM] = e4.z;
        orow[(size_t)(d + 3) * T_DIM] = e4.w;
        float d0 = e4.x - x0, d1 = e4.y - x1, d2 = e4.z - x2, d3 = e4.w - x3;
        s = fmaf(d0, d0, s);
        s = fmaf(d1, d1, s);
        s = fmaf(d2, d2, s);
        s = fmaf(d3, d3, s);
    }
    #pragma unroll
    for (int o = 16; o; o >>= 1) s += __shfl_down_sync(0xffffffffu, s, o);
    int lane = threadIdx.x & 31, w = threadIdx.x >> 5;
    if (lane == 0) warpsum[w] = s;
    __syncthreads();
    if (threadIdx.x < 8) {
        float v = warpsum[threadIdx.x];
        #pragma unroll
        for (int o = 4; o; o >>= 1) v += __shfl_down_sync(0xffu, v, o);
        if (threadIdx.x == 0)
            atomicAdd(out + LOSS_OFF, v * (0.5f / (float)Q_ELEMS));
    }
}

extern "C" void kernel_launch(void* const* d_in, const int* in_sizes, int n_in,
                              void* d_out, int out_size) {
    const float* X = (const float*)d_in[0];   // [B, D, T] fp32
    const float* E = (const float*)d_in[1];   // [K, D]    fp32
    float* out = (float*)d_out;

    enorm_kernel<<<128, 256>>>(E, out);

    size_t smem = (size_t)(D_DIM * XS_PITCH + 64 * ES_PITCH) * sizeof(float);
    cudaFuncSetAttribute(argmin_kernel, cudaFuncAttributeMaxDynamicSharedMemorySize, (int)smem);
    argmin_kernel<<<N_TOT / TN, 256, smem>>>(X, E, out);

    gather_loss_kernel<<<dim3(T_DIM / 256, B_DIM), 256>>>(X, E, out);
}

// round 4
// speedup vs baseline: 2.7181x; 2.7167x over previous
#include <cuda_runtime.h>
#include <cuda_fp16.h>
#include <cstdint>

#define B_DIM 32
#define D_DIM 256
#define T_DIM 2048
#define K_CODES 1024
#define N_TOT (B_DIM * T_DIM)
#define Q_ELEMS (B_DIM * D_DIM * T_DIM)
#define LOSS_OFF Q_ELEMS
#define IDX_OFF (Q_ELEMS + 1)
#define KEXT 768

#define XBUF (128 * 72 * 2)        // one X stage: 128 rows x 72 halves
#define EBUF (256 * 72 * 2)        // one E stage: 256 rows x 72 halves
#define OFF_ES (3 * XBUF)
#define OFF_EN (3 * XBUF + 3 * EBUF)
#define SMEM_DYN (OFF_EN + 1024)

__device__ float g_enorm[K_CODES];
__device__ unsigned long long g_best[N_TOT];
__device__ __half g_Xext[(size_t)N_TOT * KEXT];   // [n][hi|lo|hi]
__device__ __half g_Eext[(size_t)K_CODES * KEXT]; // [k][hi|hi|lo]

__device__ __forceinline__ uint32_t s2u(const void* p) {
    uint32_t a;
    asm("{ .reg .u64 t; cvta.to.shared.u64 t, %1; cvt.u32.u64 %0, t; }" : "=r"(a) : "l"(p));
    return a;
}
__device__ __forceinline__ void cp16(uint32_t d, const void* s) {
    asm volatile("cp.async.cg.shared.global [%0], [%1], 16;" :: "r"(d), "l"(s) : "memory");
}
__device__ __forceinline__ uint4 ldsm4(uint32_t a) {
    uint4 r;
    asm volatile("ldmatrix.sync.aligned.m8n8.x4.shared.b16 {%0,%1,%2,%3}, [%4];"
                 : "=r"(r.x), "=r"(r.y), "=r"(r.z), "=r"(r.w) : "r"(a));
    return r;
}
__device__ __forceinline__ void mma16816(float* d, uint4 a, uint32_t b0, uint32_t b1) {
    asm volatile("mma.sync.aligned.m16n8k16.row.col.f32.f16.f16.f32 "
                 "{%0,%1,%2,%3},{%4,%5,%6,%7},{%8,%9},{%0,%1,%2,%3};"
                 : "+f"(d[0]), "+f"(d[1]), "+f"(d[2]), "+f"(d[3])
                 : "r"(a.x), "r"(a.y), "r"(a.z), "r"(a.w), "r"(b0), "r"(b1));
}
__device__ __forceinline__ uint32_t mono(float f) {
    uint32_t u = __float_as_uint(f);
    return (u & 0x80000000u) ? ~u : (u | 0x80000000u);
}

// X [B,D,T] -> fp16 split rows [n][hi(256)|lo(256)|hi(256)]; also init g_best.
__global__ void __launch_bounds__(256) xprep_kernel(const float* __restrict__ X) {
    __shared__ float tile[256][33];
    int gt = (blockIdx.y * gridDim.x + blockIdx.x) * 256 + threadIdx.x;
    if (gt < N_TOT) g_best[gt] = ~0ull;
    int lane = threadIdx.x & 31, w = threadIdx.x >> 5;
    const float* src = X + (size_t)blockIdx.y * D_DIM * T_DIM + blockIdx.x * 32;
    #pragma unroll 8
    for (int r = 0; r < 32; r++) {
        int d = w + r * 8;
        tile[d][lane] = src[(size_t)d * T_DIM + lane];
    }
    __syncthreads();
    for (int i = 0; i < 4; i++) {
        int nl = w * 4 + i;
        int n = blockIdx.y * T_DIM + blockIdx.x * 32 + nl;
        __align__(16) __half hb[8], lb[8];
        #pragma unroll
        for (int q = 0; q < 8; q++) {
            float x = tile[lane * 8 + q][nl];
            __half h = __float2half_rn(x);
            hb[q] = h;
            lb[q] = __float2half_rn(x - __half2float(h));
        }
        __half* row = g_Xext + (size_t)n * KEXT;
        *(uint4*)(row + lane * 8) = *(uint4*)hb;
        *(uint4*)(row + 256 + lane * 8) = *(uint4*)lb;
        *(uint4*)(row + 512 + lane * 8) = *(uint4*)hb;
    }
}

// E [K,D] -> [k][hi|hi|lo], exact 0.5||e||^2, loss init.
__global__ void __launch_bounds__(256) eprep_kernel(const float* __restrict__ E, float* __restrict__ out) {
    if (blockIdx.x == 0 && threadIdx.x == 0) out[LOSS_OFF] = 0.0f;
    int k = blockIdx.x * 8 + (threadIdx.x >> 5);
    int lane = threadIdx.x & 31;
    const float* er = E + (size_t)k * D_DIM;
    __align__(16) __half hb[8], lb[8];
    float s = 0.f;
    #pragma unroll
    for (int q = 0; q < 8; q++) {
        float x = er[lane * 8 + q];
        s = fmaf(x, x, s);
        __half h = __float2half_rn(x);
        hb[q] = h;
        lb[q] = __float2half_rn(x - __half2float(h));
    }
    __half* row = g_Eext + (size_t)k * KEXT;
    *(uint4*)(row + lane * 8) = *(uint4*)hb;
    *(uint4*)(row + 256 + lane * 8) = *(uint4*)hb;
    *(uint4*)(row + 512 + lane * 8) = *(uint4*)lb;
    #pragma unroll
    for (int o = 16; o; o >>= 1) s += __shfl_down_sync(0xffffffffu, s, o);
    if (lane == 0) g_enorm[k] = 0.5f * s;
}

// Distance-argmin GEMM: CTA tile = 128 rows x 256 codes, K=768 streamed.
__global__ void __launch_bounds__(256, 1) vqmma_kernel() {
    extern __shared__ char sm[];
    const uint32_t sb = s2u(sm);
    float* en_s = (float*)(sm + OFF_EN);
    const int tid = threadIdx.x, wid = tid >> 5, lane = tid & 31;
    const int n0 = blockIdx.x * 128, k0 = blockIdx.y * 256;
    const int mw = wid & 1, nw = wid >> 1;

    en_s[tid] = g_enorm[k0 + tid];

    float acc[128];
    #pragma unroll
    for (int i = 0; i < 128; i++) acc[i] = 0.f;

    auto load = [&](int kc) {
        int buf = kc % 3;
        const __half* xs = g_Xext + (size_t)n0 * KEXT + kc * 64;
        const __half* es = g_Eext + (size_t)k0 * KEXT + kc * 64;
        uint32_t xb = sb + buf * XBUF;
        uint32_t eb = sb + OFF_ES + buf * EBUF;
        #pragma unroll
        for (int q = 0; q < 4; q++) {
            int id = tid + q * 256, r = id >> 3, c = id & 7;
            cp16(xb + (r * 72 + c * 8) * 2, xs + (size_t)r * KEXT + c * 8);
        }
        #pragma unroll
        for (int q = 0; q < 8; q++) {
            int id = tid + q * 256, r = id >> 3, c = id & 7;
            cp16(eb + (r * 72 + c * 8) * 2, es + (size_t)r * KEXT + c * 8);
        }
        asm volatile("cp.async.commit_group;" ::: "memory");
    };

    load(0); load(1); load(2);

    const int l7 = lane & 7;
    const int arow = ((lane >> 3) & 1) * 8, akc = (lane >> 4) * 8;   // A: row+,k+
    const int brow = (lane >> 4) * 8, bkc = ((lane >> 3) & 1) * 8;   // B: code+,k+

    for (int kc = 0; kc < 12; kc++) {
        if (kc < 10)      asm volatile("cp.async.wait_group 2;" ::: "memory");
        else if (kc == 10) asm volatile("cp.async.wait_group 1;" ::: "memory");
        else               asm volatile("cp.async.wait_group 0;" ::: "memory");
        __syncthreads();
        int buf = kc % 3;
        uint32_t xb = sb + buf * XBUF;
        uint32_t eb = sb + OFF_ES + buf * EBUF;
        #pragma unroll
        for (int ks = 0; ks < 4; ks++) {
            int kk = ks * 16;
            uint4 B[4];
            #pragma unroll
            for (int p = 0; p < 4; p++) {
                int nb = nw * 64 + p * 16;
                B[p] = ldsm4(eb + ((nb + l7 + brow) * 72 + kk + bkc) * 2);
            }
            #pragma unroll
            for (int mt = 0; mt < 4; mt++) {
                int m0 = mw * 64 + mt * 16;
                uint4 A = ldsm4(xb + ((m0 + l7 + arow) * 72 + kk + akc) * 2);
                #pragma unroll
                for (int p = 0; p < 4; p++) {
                    mma16816(&acc[(mt * 8 + p * 2 + 0) * 4], A, B[p].x, B[p].y);
                    mma16816(&acc[(mt * 8 + p * 2 + 1) * 4], A, B[p].z, B[p].w);
                }
            }
        }
        __syncthreads();
        if (kc + 3 < 12) load(kc + 3);
    }

    // Argmin epilogue: pack (monotone score, code) and atomicMin per row.
    #pragma unroll
    for (int mt = 0; mt < 4; mt++) {
        #pragma unroll
        for (int h = 0; h < 2; h++) {
            unsigned long long best = ~0ull;
            #pragma unroll
            for (int nt = 0; nt < 8; nt++) {
                #pragma unroll
                for (int c2 = 0; c2 < 2; c2++) {
                    int cl = nw * 64 + nt * 8 + (lane & 3) * 2 + c2;
                    float sc = en_s[cl] - acc[(mt * 8 + nt) * 4 + h * 2 + c2];
                    unsigned long long p = ((unsigned long long)mono(sc) << 32) | (unsigned)(k0 + cl);
                    if (p < best) best = p;
                }
            }
            unsigned long long o1 = __shfl_xor_sync(0xffffffffu, best, 1);
            if (o1 < best) best = o1;
            unsigned long long o2 = __shfl_xor_sync(0xffffffffu, best, 2);
            if (o2 < best) best = o2;
            if ((lane & 3) == 0) {
                int row = n0 + mw * 64 + mt * 16 + (lane >> 2) + h * 8;
                atomicMin(&g_best[row], best);
            }
        }
    }
}

// Gather codebook rows, write quantized [B,D,T] + idx, accumulate loss.
__global__ void __launch_bounds__(256) gather_loss_kernel(const float* __restrict__ X,
                                                          const float* __restrict__ E,
                                                          float* __restrict__ out) {
    __shared__ float ws[8];
    int t = blockIdx.x * 256 + threadIdx.x, b = blockIdx.y;
    int n = b * T_DIM + t;
    int j = (int)(unsigned)(g_best[n] & 0xffffffffull);
    out[IDX_OFF + n] = (float)j;
    const float* er = E + (size_t)j * D_DIM;
    const float* xr = X + (size_t)b * D_DIM * T_DIM + t;
    float* orow = out + (size_t)b * D_DIM * T_DIM + t;
    float s = 0.f;
    #pragma unroll 8
    for (int d = 0; d < D_DIM; d += 4) {
        float4 e4 = *(const float4*)(er + d);
        float x0 = xr[(size_t)(d + 0) * T_DIM], x1 = xr[(size_t)(d + 1) * T_DIM];
        float x2 = xr[(size_t)(d + 2) * T_DIM], x3 = xr[(size_t)(d + 3) * T_DIM];
        orow[(size_t)(d + 0) * T_DIM] = e4.x;
        orow[(size_t)(d + 1) * T_DIM] = e4.y;
        orow[(size_t)(d + 2) * T_DIM] = e4.z;
        orow[(size_t)(d + 3) * T_DIM] = e4.w;
        float d0 = e4.x - x0, d1 = e4.y - x1, d2 = e4.z - x2, d3 = e4.w - x3;
        s = fmaf(d0, d0, s); s = fmaf(d1, d1, s); s = fmaf(d2, d2, s); s = fmaf(d3, d3, s);
    }
    #pragma unroll
    for (int o = 16; o; o >>= 1) s += __shfl_down_sync(0xffffffffu, s, o);
    if ((threadIdx.x & 31) == 0) ws[threadIdx.x >> 5] = s;
    __syncthreads();
    if (threadIdx.x < 8) {
        float v = ws[threadIdx.x];
        #pragma unroll
        for (int o = 4; o; o >>= 1) v += __shfl_down_sync(0xffu, v, o);
        if (threadIdx.x == 0) atomicAdd(out + LOSS_OFF, v * (0.5f / (float)Q_ELEMS));
    }
}

extern "C" void kernel_launch(void* const* d_in, const int* in_sizes, int n_in,
                              void* d_out, int out_size) {
    const float* X = (const float*)d_in[0];
    const float* E = (const float*)d_in[1];
    float* out = (float*)d_out;
    eprep_kernel<<<K_CODES / 8, 256>>>(E, out);
    xprep_kernel<<<dim3(T_DIM / 32, B_DIM), 256>>>(X);
    cudaFuncSetAttribute(vqmma_kernel, cudaFuncAttributeMaxDynamicSharedMemorySize, SMEM_DYN);
    vqmma_kernel<<<dim3(N_TOT / 128, K_CODES / 256), 256, SMEM_DYN>>>();
    gather_loss_kernel<<<dim3(T_DIM / 256, B_DIM), 256>>>(X, E, out);
}

// round 5
// speedup vs baseline: 2.9895x; 1.0998x over previous
#include <cuda_runtime.h>
#include <cuda_fp16.h>
#include <cstdint>

#define B_DIM 32
#define D_DIM 256
#define T_DIM 2048
#define K_CODES 1024
#define N_TOT (B_DIM * T_DIM)
#define Q_ELEMS (B_DIM * D_DIM * T_DIM)
#define LOSS_OFF Q_ELEMS
#define IDX_OFF (Q_ELEMS + 1)
#define KEXT 768

#define XBUF (128 * 72 * 2)        // one X stage: 128 rows x 72 halves
#define EBUF (256 * 72 * 2)        // one E stage: 256 rows x 72 halves
#define NSTAGE 4
#define OFF_ES (NSTAGE * XBUF)
#define OFF_EN (NSTAGE * XBUF + NSTAGE * EBUF)
#define SMEM_DYN (OFF_EN + 1024)

__device__ float g_enorm[K_CODES];
__device__ unsigned long long g_best[N_TOT];
__device__ __half g_Xext[(size_t)N_TOT * KEXT];   // [n][hi|lo|hi]
__device__ __half g_Eext[(size_t)K_CODES * KEXT]; // [k][hi|hi|lo]

__device__ __forceinline__ uint32_t s2u(const void* p) {
    uint32_t a;
    asm("{ .reg .u64 t; cvta.to.shared.u64 t, %1; cvt.u32.u64 %0, t; }" : "=r"(a) : "l"(p));
    return a;
}
__device__ __forceinline__ void cp16(uint32_t d, const void* s) {
    asm volatile("cp.async.cg.shared.global [%0], [%1], 16;" :: "r"(d), "l"(s) : "memory");
}
__device__ __forceinline__ uint4 ldsm4(uint32_t a) {
    uint4 r;
    asm volatile("ldmatrix.sync.aligned.m8n8.x4.shared.b16 {%0,%1,%2,%3}, [%4];"
                 : "=r"(r.x), "=r"(r.y), "=r"(r.z), "=r"(r.w) : "r"(a));
    return r;
}
__device__ __forceinline__ void mma16816(float* d, uint4 a, uint32_t b0, uint32_t b1) {
    asm volatile("mma.sync.aligned.m16n8k16.row.col.f32.f16.f16.f32 "
                 "{%0,%1,%2,%3},{%4,%5,%6,%7},{%8,%9},{%0,%1,%2,%3};"
                 : "+f"(d[0]), "+f"(d[1]), "+f"(d[2]), "+f"(d[3])
                 : "r"(a.x), "r"(a.y), "r"(a.z), "r"(a.w), "r"(b0), "r"(b1));
}
__device__ __forceinline__ uint32_t mono(float f) {
    uint32_t u = __float_as_uint(f);
    return (u & 0x80000000u) ? ~u : (u | 0x80000000u);
}

// X [B,D,T] -> fp16 split rows [n][hi(256)|lo(256)|hi(256)]; also init g_best.
__global__ void __launch_bounds__(256) xprep_kernel(const float* __restrict__ X) {
    __shared__ float tile[256][33];
    int gt = (blockIdx.y * gridDim.x + blockIdx.x) * 256 + threadIdx.x;
    if (gt < N_TOT) g_best[gt] = ~0ull;
    int lane = threadIdx.x & 31, w = threadIdx.x >> 5;
    const float* src = X + (size_t)blockIdx.y * D_DIM * T_DIM + blockIdx.x * 32;
    #pragma unroll 8
    for (int r = 0; r < 32; r++) {
        int d = w + r * 8;
        tile[d][lane] = src[(size_t)d * T_DIM + lane];
    }
    __syncthreads();
    for (int i = 0; i < 4; i++) {
        int nl = w * 4 + i;
        int n = blockIdx.y * T_DIM + blockIdx.x * 32 + nl;
        __align__(16) __half hb[8], lb[8];
        #pragma unroll
        for (int q = 0; q < 8; q++) {
            float x = tile[lane * 8 + q][nl];
            __half h = __float2half_rn(x);
            hb[q] = h;
            lb[q] = __float2half_rn(x - __half2float(h));
        }
        __half* row = g_Xext + (size_t)n * KEXT;
        *(uint4*)(row + lane * 8) = *(uint4*)hb;
        *(uint4*)(row + 256 + lane * 8) = *(uint4*)lb;
        *(uint4*)(row + 512 + lane * 8) = *(uint4*)hb;
    }
}

// E [K,D] -> [k][hi|hi|lo], exact 0.5||e||^2, loss init.
__global__ void __launch_bounds__(256) eprep_kernel(const float* __restrict__ E, float* __restrict__ out) {
    if (blockIdx.x == 0 && threadIdx.x == 0) out[LOSS_OFF] = 0.0f;
    int k = blockIdx.x * 8 + (threadIdx.x >> 5);
    int lane = threadIdx.x & 31;
    const float* er = E + (size_t)k * D_DIM;
    __align__(16) __half hb[8], lb[8];
    float s = 0.f;
    #pragma unroll
    for (int q = 0; q < 8; q++) {
        float x = er[lane * 8 + q];
        s = fmaf(x, x, s);
        __half h = __float2half_rn(x);
        hb[q] = h;
        lb[q] = __float2half_rn(x - __half2float(h));
    }
    __half* row = g_Eext + (size_t)k * KEXT;
    *(uint4*)(row + lane * 8) = *(uint4*)hb;
    *(uint4*)(row + 256 + lane * 8) = *(uint4*)hb;
    *(uint4*)(row + 512 + lane * 8) = *(uint4*)lb;
    #pragma unroll
    for (int o = 16; o; o >>= 1) s += __shfl_down_sync(0xffffffffu, s, o);
    if (lane == 0) g_enorm[k] = 0.5f * s;
}

// Distance-argmin GEMM: CTA tile = 128 rows x 256 codes, K=768 streamed.
// 4-stage cp.async pipeline, one __syncthreads per chunk.
__global__ void __launch_bounds__(256, 1) vqmma_kernel() {
    extern __shared__ char sm[];
    const uint32_t sb = s2u(sm);
    float* en_s = (float*)(sm + OFF_EN);
    const int tid = threadIdx.x, wid = tid >> 5, lane = tid & 31;
    const int n0 = blockIdx.x * 128, k0 = blockIdx.y * 256;
    const int mw = wid & 1, nw = wid >> 1;

    en_s[tid] = g_enorm[k0 + tid];

    float acc[128];
    #pragma unroll
    for (int i = 0; i < 128; i++) acc[i] = 0.f;

    auto load = [&](int kc) {
        int buf = kc & 3;
        const __half* xs = g_Xext + (size_t)n0 * KEXT + kc * 64;
        const __half* es = g_Eext + (size_t)k0 * KEXT + kc * 64;
        uint32_t xb = sb + buf * XBUF;
        uint32_t eb = sb + OFF_ES + buf * EBUF;
        #pragma unroll
        for (int q = 0; q < 4; q++) {
            int id = tid + q * 256, r = id >> 3, c = id & 7;
            cp16(xb + (r * 72 + c * 8) * 2, xs + (size_t)r * KEXT + c * 8);
        }
        #pragma unroll
        for (int q = 0; q < 8; q++) {
            int id = tid + q * 256, r = id >> 3, c = id & 7;
            cp16(eb + (r * 72 + c * 8) * 2, es + (size_t)r * KEXT + c * 8);
        }
        asm volatile("cp.async.commit_group;" ::: "memory");
    };

    load(0); load(1); load(2);

    const int l7 = lane & 7;
    const int arow = ((lane >> 3) & 1) * 8, akc = (lane >> 4) * 8;   // A: row+,k+
    const int brow = (lane >> 4) * 8, bkc = ((lane >> 3) & 1) * 8;   // B: code+,k+

    for (int kc = 0; kc < 12; kc++) {
        if (kc < 10)       asm volatile("cp.async.wait_group 2;" ::: "memory");
        else if (kc == 10) asm volatile("cp.async.wait_group 1;" ::: "memory");
        else               asm volatile("cp.async.wait_group 0;" ::: "memory");
        __syncthreads();
        int buf = kc & 3;
        uint32_t xb = sb + buf * XBUF;
        uint32_t eb = sb + OFF_ES + buf * EBUF;
        #pragma unroll
        for (int ks = 0; ks < 4; ks++) {
            int kk = ks * 16;
            uint4 B[4];
            #pragma unroll
            for (int p = 0; p < 4; p++) {
                int nb = nw * 64 + p * 16;
                B[p] = ldsm4(eb + ((nb + l7 + brow) * 72 + kk + bkc) * 2);
            }
            #pragma unroll
            for (int mt = 0; mt < 4; mt++) {
                int m0 = mw * 64 + mt * 16;
                uint4 A = ldsm4(xb + ((m0 + l7 + arow) * 72 + kk + akc) * 2);
                #pragma unroll
                for (int p = 0; p < 4; p++) {
                    mma16816(&acc[(mt * 8 + p * 2 + 0) * 4], A, B[p].x, B[p].y);
                    mma16816(&acc[(mt * 8 + p * 2 + 1) * 4], A, B[p].z, B[p].w);
                }
            }
        }
        // Safe without a second barrier: buffer (kc+3)&3 == (kc-1)&3 was
        // fully consumed by compute(kc-1), and every thread passed this
        // iteration's top barrier after finishing compute(kc-1).
        if (kc + 3 < 12) load(kc + 3);
    }

    // Argmin epilogue: pack (monotone score, code) and atomicMin per row.
    #pragma unroll
    for (int mt = 0; mt < 4; mt++) {
        #pragma unroll
        for (int h = 0; h < 2; h++) {
            unsigned long long best = ~0ull;
            #pragma unroll
            for (int nt = 0; nt < 8; nt++) {
                #pragma unroll
                for (int c2 = 0; c2 < 2; c2++) {
                    int cl = nw * 64 + nt * 8 + (lane & 3) * 2 + c2;
                    float sc = en_s[cl] - acc[(mt * 8 + nt) * 4 + h * 2 + c2];
                    unsigned long long p = ((unsigned long long)mono(sc) << 32) | (unsigned)(k0 + cl);
                    if (p < best) best = p;
                }
            }
            unsigned long long o1 = __shfl_xor_sync(0xffffffffu, best, 1);
            if (o1 < best) best = o1;
            unsigned long long o2 = __shfl_xor_sync(0xffffffffu, best, 2);
            if (o2 < best) best = o2;
            if ((lane & 3) == 0) {
                int row = n0 + mw * 64 + mt * 16 + (lane >> 2) + h * 8;
                atomicMin(&g_best[row], best);
            }
        }
    }
}

// Gather codebook rows, write quantized [B,D,T] + idx, accumulate loss.
__global__ void __launch_bounds__(128) gather_loss_kernel(const float* __restrict__ X,
                                                          const float* __restrict__ E,
                                                          float* __restrict__ out) {
    __shared__ float ws[4];
    int t = blockIdx.x * 128 + threadIdx.x, b = blockIdx.y;
    int n = b * T_DIM + t;
    int j = (int)(unsigned)(g_best[n] & 0xffffffffull);
    out[IDX_OFF + n] = (float)j;
    const float* er = E + (size_t)j * D_DIM;
    const float* xr = X + (size_t)b * D_DIM * T_DIM + t;
    float* orow = out + (size_t)b * D_DIM * T_DIM + t;
    float s = 0.f;
    #pragma unroll 8
    for (int d = 0; d < D_DIM; d += 4) {
        float4 e4 = *(const float4*)(er + d);
        float x0 = xr[(size_t)(d + 0) * T_DIM], x1 = xr[(size_t)(d + 1) * T_DIM];
        float x2 = xr[(size_t)(d + 2) * T_DIM], x3 = xr[(size_t)(d + 3) * T_DIM];
        orow[(size_t)(d + 0) * T_DIM] = e4.x;
        orow[(size_t)(d + 1) * T_DIM] = e4.y;
        orow[(size_t)(d + 2) * T_DIM] = e4.z;
        orow[(size_t)(d + 3) * T_DIM] = e4.w;
        float d0 = e4.x - x0, d1 = e4.y - x1, d2 = e4.z - x2, d3 = e4.w - x3;
        s = fmaf(d0, d0, s); s = fmaf(d1, d1, s); s = fmaf(d2, d2, s); s = fmaf(d3, d3, s);
    }
    #pragma unroll
    for (int o = 16; o; o >>= 1) s += __shfl_down_sync(0xffffffffu, s, o);
    if ((threadIdx.x & 31) == 0) ws[threadIdx.x >> 5] = s;
    __syncthreads();
    if (threadIdx.x < 4) {
        float v = ws[threadIdx.x];
        v += __shfl_down_sync(0xfu, v, 2);
        v += __shfl_down_sync(0xfu, v, 1);
        if (threadIdx.x == 0) atomicAdd(out + LOSS_OFF, v * (0.5f / (float)Q_ELEMS));
    }
}

extern "C" void kernel_launch(void* const* d_in, const int* in_sizes, int n_in,
                              void* d_out, int out_size) {
    const float* X = (const float*)d_in[0];
    const float* E = (const float*)d_in[1];
    float* out = (float*)d_out;
    eprep_kernel<<<K_CODES / 8, 256>>>(E, out);
    xprep_kernel<<<dim3(T_DIM / 32, B_DIM), 256>>>(X);
    cudaFuncSetAttribute(vqmma_kernel, cudaFuncAttributeMaxDynamicSharedMemorySize, SMEM_DYN);
    vqmma_kernel<<<dim3(N_TOT / 128, K_CODES / 256), 256, SMEM_DYN>>>();
    gather_loss_kernel<<<dim3(T_DIM / 128, B_DIM), 128>>>(X, E, out);
}